// round 2
// baseline (speedup 1.0000x reference)
#include <cuda_runtime.h>
#include <cuda_bf16.h>

#define BATCH 32
#define SEQ   2048
#define EDIM  128
#define HVOC  500000
#define HBASE 257
#define NPOS  (BATCH * SEQ)

// One warp per PAIR of consecutive (b, s) positions.
//  - 12 independent 512B gathers in flight per warp (was 6)
//  - two independent rolling-hash chains (ILP=2 in the integer prologue)
//  - __ldcg gathers (bypass L1 — rows are use-once), __stcs streaming stores
__global__ __launch_bounds__(256) void ngram_embed_kernel(
    const int* __restrict__ tokens,     // (B, S) int32
    const float* __restrict__ tables,   // (6, V, D) fp32
    float* __restrict__ out)            // (B, S, D) fp32
{
    const int gwarp = (blockIdx.x * blockDim.x + threadIdx.x) >> 5;
    const int lane  = threadIdx.x & 31;
    const int p0    = gwarp << 1;          // first position of the pair
    if (p0 >= NPOS) return;

    const int b  = p0 >> 11;               // / SEQ   (SEQ even -> pair shares row)
    const int s0 = p0 & (SEQ - 1);
    const int s1 = s0 + 1;

    const int* __restrict__ trow = tokens + (long)b * SEQ;

    // Context bytes t[s1-8 .. s1]; t[i] for i<0 reads as 0 (masked by pos test).
    int t[9];
#pragma unroll
    for (int j = 0; j <= 8; j++) {
        const int i = s1 - j;
        t[j] = (i >= 0) ? __ldg(&trow[i]) : 0;   // t[0]=x[s1], t[1]=x[s0], ...
    }
    const int x0 = t[1];   // raw byte at s0
    const int x1 = t[0];   // raw byte at s1

    // Two independent rolling-hash chains.
    // chain0 starts at s0 (t[1]), consumes t[2..8]; chain1 at s1 (t[0]), consumes t[1..7].
    int idx0[6], idx1[6];
    int h0 = x0, h1 = x1;
#pragma unroll
    for (int j = 1; j <= 7; j++) {
        h0 = (h0 * HBASE + t[j + 1]) % HVOC;
        h1 = (h1 * HBASE + t[j])     % HVOC;
        if (j >= 2) {                        // n = j+1, valid when s >= j
            idx0[j - 2] = (s0 >= j) ? h0 : x0;
            idx1[j - 2] = (s1 >= j) ? h1 : x1;
        }
    }

    // 12 independent 512B gathers (one float4/lane each), accumulate per position.
    float4 a0 = make_float4(0.f, 0.f, 0.f, 0.f);
    float4 a1 = make_float4(0.f, 0.f, 0.f, 0.f);
#pragma unroll
    for (int k = 0; k < 6; k++) {
        const float4* __restrict__ base = reinterpret_cast<const float4*>(
            tables + (long)k * ((long)HVOC * EDIM));
        const float4 v0 = __ldcg(&base[(long)idx0[k] * (EDIM / 4) + lane]);
        const float4 v1 = __ldcg(&base[(long)idx1[k] * (EDIM / 4) + lane]);
        a0.x += v0.x; a0.y += v0.y; a0.z += v0.z; a0.w += v0.w;
        a1.x += v1.x; a1.y += v1.y; a1.z += v1.z; a1.w += v1.w;
    }

    const float inv6 = 1.0f / 6.0f;
    a0.x *= inv6; a0.y *= inv6; a0.z *= inv6; a0.w *= inv6;
    a1.x *= inv6; a1.y *= inv6; a1.z *= inv6; a1.w *= inv6;

    float4* __restrict__ o = reinterpret_cast<float4*>(out + (long)p0 * EDIM);
    __stcs(&o[lane], a0);
    __stcs(&o[(EDIM / 4) + lane], a1);
}

extern "C" void kernel_launch(void* const* d_in, const int* in_sizes, int n_in,
                              void* d_out, int out_size) {
    const int*   tokens = (const int*)d_in[0];
    const float* tables = (const float*)d_in[1];
    float*       out    = (float*)d_out;

    const int threads = 256;                    // 8 warps = 16 positions / block
    const int pairs   = NPOS / 2;               // 32768 warps total
    const int warps_per_block = threads / 32;
    const int blocks = (pairs + warps_per_block - 1) / warps_per_block;
    ngram_embed_kernel<<<blocks, threads>>>(tokens, tables, out);
}